// round 17
// baseline (speedup 1.0000x reference)
#include <cuda_runtime.h>
#include <cuda_bf16.h>
#include <cstdint>
#include <math.h>

// Problem constants
#define Bz 4
#define Sz 2048
#define Dz 2048
#define NHz 16
#define DHz 128

#define TOT (4UL*2048UL*2048UL)   // B*S*D elements

// Scratch (allocation-free rule: __device__ globals)
__device__ float g_Q[TOT];
__device__ float g_K[TOT];
__device__ float g_V[TOT];
__device__ float g_A[TOT];
__device__ float g_R[TOT];
__device__ float g_KVc[TOT];      // compacted kv_input
__device__ int   g_cidx[Bz * Sz];
__device__ int   g_cnt[Bz];

// ===========================================================================
// tf32 helpers (base-family PTX, assembles for plain compute_103)
// ===========================================================================
__device__ __forceinline__ float tf32r(float x) {
    uint32_t u;
    asm("cvt.rna.tf32.f32 %0, %1;" : "=r"(u) : "f"(x));
    return __uint_as_float(u);
}
__device__ __forceinline__ void mma_tf32(float* c, const uint32_t* a, const uint32_t* b) {
    asm volatile(
        "mma.sync.aligned.m16n8k8.row.col.f32.tf32.tf32.f32 "
        "{%0,%1,%2,%3}, {%4,%5,%6,%7}, {%8,%9}, {%0,%1,%2,%3};"
        : "+f"(c[0]), "+f"(c[1]), "+f"(c[2]), "+f"(c[3])
        : "r"(a[0]), "r"(a[1]), "r"(a[2]), "r"(a[3]), "r"(b[0]), "r"(b[1]));
}

// ===========================================================================
// Mask compaction
// ===========================================================================
__global__ __launch_bounds__(1024) void compact_kernel(
    const int* __restrict__ mask, int* __restrict__ cidx, int* __restrict__ cnt)
{
    __shared__ int ssum[1024];
    const int b = blockIdx.x, t = threadIdx.x;
    const int* m = mask + b * Sz;
    int u0 = (m[2 * t] == 0) ? 1 : 0;
    int u1 = (m[2 * t + 1] == 0) ? 1 : 0;
    int pair = u0 + u1;
    ssum[t] = pair;
    __syncthreads();
#pragma unroll
    for (int d = 1; d < 1024; d <<= 1) {
        int v = (t >= d) ? ssum[t - d] : 0;
        __syncthreads();
        ssum[t] += v;
        __syncthreads();
    }
    int excl = ssum[t] - pair;
    if (u0) cidx[b * Sz + excl] = 2 * t;
    if (u1) cidx[b * Sz + excl + u0] = 2 * t + 1;
    if (t == 1023) cnt[b] = ssum[1023];
}

__global__ __launch_bounds__(256) void gather_kernel(
    const float* __restrict__ kv, const int* __restrict__ cidx,
    const int* __restrict__ cnt, float* __restrict__ out)
{
    const int row = blockIdx.x;              // 0..8191
    const int b = row >> 11, r = row & 2047;
    const int n = cnt[b];
    float4* dst = (float4*)(out + (long)row * Dz);
    if (r < n) {
        const float4* src = (const float4*)(kv + ((long)(b * Sz + cidx[b * Sz + r])) * Dz);
#pragma unroll 2
        for (int i = threadIdx.x; i < 512; i += 256) dst[i] = src[i];
    } else {
        float4 z = {0.f, 0.f, 0.f, 0.f};
#pragma unroll 2
        for (int i = threadIdx.x; i < 512; i += 256) dst[i] = z;
    }
}

// ===========================================================================
// tf32 GEMM, 128x256 CTA tile, warp tile 64x64 (2x4 warp grid), frag-major
// smem, double-buffered, one barrier per chunk. 1 CTA/SM (dynamic smem 49KB).
//   A stage: [kb(2)][sub(8)][lane(32)][reg(4)]                2048 f
//   B stage: [kb(2)][nt(32)*66 + (nn*4+(kk&3))*2 + (kk>>2)]   4224 f
// ===========================================================================
#define A_KB_STRIDE 1024
#define A_STAGE     2048
#define B_NT_STRIDE 66
#define B_KB_STRIDE (32 * B_NT_STRIDE)    // 2112
#define B_STAGE     (2 * B_KB_STRIDE)     // 4224
#define TG_SMEM ((2 * A_STAGE + 2 * B_STAGE) * 4)   // 50176 B

__global__ __launch_bounds__(256) void tgemm(
    const float* __restrict__ A,
    const float* __restrict__ Bx, const float* __restrict__ By,
    const float* __restrict__ Res, float* __restrict__ Cx, float* __restrict__ Cy,
    const int* __restrict__ cnt)
{
    const float* __restrict__ B = blockIdx.z ? By : Bx;
    float* __restrict__ C = blockIdx.z ? Cy : Cx;

    const int m0 = blockIdx.y * 128, n0 = blockIdx.x * 256;
    if (cnt) {
        int b = m0 >> 11, local = m0 & 2047;
        if (local >= cnt[b]) return;
    }

    extern __shared__ float sdyn[];
    float* sA = sdyn;                     // 2 stages x 2048
    float* sB = sdyn + 2 * A_STAGE;       // 2 stages x 4224

    const int tid = threadIdx.x;
    const int lane = tid & 31, wid = tid >> 5;
    const int wm = wid >> 2, wn = wid & 3;          // 2 x 4 warp grid

    // A producer constants
    const int rrA = tid >> 4, colA = tid & 15;
    const int kbA = colA >> 3, cA = colA & 7;
    const int constA = kbA * A_KB_STRIDE
                     + ((rrA & 7) * 4 + (cA & 3)) * 4
                     + (rrA >> 3) + 2 * (cA >> 2);
    // B producer constants: n = nB (+128), k = r*2 + hiB
    const int nB = tid & 127, hiB = tid >> 7;

    float acc[4][8][4];
#pragma unroll
    for (int mi = 0; mi < 4; mi++)
#pragma unroll
        for (int ni = 0; ni < 8; ni++)
#pragma unroll
            for (int e = 0; e < 4; e++) acc[mi][ni][e] = 0.f;

    float ra[8], rb[16];

    auto ldg = [&](int k0) {
#pragma unroll
        for (int r = 0; r < 8; r++)
            ra[r] = A[(long)(m0 + r * 16 + rrA) * 2048 + k0 + colA];
#pragma unroll
        for (int r = 0; r < 8; r++) {
            long base = (long)(k0 + r * 2 + hiB) * 2048 + n0 + nB;
            rb[2 * r]     = B[base];
            rb[2 * r + 1] = B[base + 128];
        }
    };
    auto sts = [&](int st) {
        float* sAs = sA + st * A_STAGE;
        float* sBs = sB + st * B_STAGE;
#pragma unroll
        for (int r = 0; r < 8; r++)
            sAs[constA + r * 128] = tf32r(ra[r]);
#pragma unroll
        for (int r = 0; r < 8; r++) {
            int k = r * 2 + hiB;
            int kb = k >> 3, kk = k & 7;
            int roff = (kk & 3) * 2 + (kk >> 2);
#pragma unroll
            for (int hf = 0; hf < 2; hf++) {
                int n = nB + hf * 128;
                int addr = kb * B_KB_STRIDE + (n >> 3) * B_NT_STRIDE
                         + (n & 7) * 8 + roff;
                sBs[addr] = tf32r(rb[2 * r + hf]);
            }
        }
    };

    ldg(0);
    sts(0);
    __syncthreads();

    for (int c = 0; c < 128; c++) {
        const int st = c & 1;
        float* sAs = sA + st * A_STAGE;
        float* sBs = sB + st * B_STAGE;
        if (c + 1 < 128) ldg((c + 1) * 16);

#pragma unroll
        for (int kb = 0; kb < 2; kb++) {
            uint4 af[4];
            uint2 bf[8];
#pragma unroll
            for (int mi = 0; mi < 4; mi++)
                af[mi] = *(const uint4*)&sAs[kb * A_KB_STRIDE
                                             + (wm * 4 + mi) * 128 + lane * 4];
#pragma unroll
            for (int ni = 0; ni < 8; ni++)
                bf[ni] = *(const uint2*)&sBs[kb * B_KB_STRIDE
                                             + (wn * 8 + ni) * B_NT_STRIDE + lane * 2];
#pragma unroll
            for (int mi = 0; mi < 4; mi++)
#pragma unroll
                for (int ni = 0; ni < 8; ni++)
                    mma_tf32(acc[mi][ni], (const uint32_t*)&af[mi],
                             (const uint32_t*)&bf[ni]);
        }

        if (c + 1 < 128) {
            sts((c + 1) & 1);    // other stage; prev barrier ordered readers
            __syncthreads();
        }
    }

    const int gg = lane >> 2, tt = lane & 3;
#pragma unroll
    for (int mi = 0; mi < 4; mi++) {
        int r0 = m0 + wm * 64 + mi * 16 + gg;
#pragma unroll
        for (int ni = 0; ni < 8; ni++) {
            int col = n0 + wn * 64 + ni * 8 + tt * 2;
            long o0 = (long)r0 * 2048 + col;
            long o1 = (long)(r0 + 8) * 2048 + col;
            float2 v0 = { acc[mi][ni][0], acc[mi][ni][1] };
            float2 v1 = { acc[mi][ni][2], acc[mi][ni][3] };
            if (Res) {
                float2 q0 = *(const float2*)&Res[o0];
                float2 q1 = *(const float2*)&Res[o1];
                v0.x += q0.x; v0.y += q0.y;
                v1.x += q1.x; v1.y += q1.y;
            }
            *(float2*)&C[o0] = v0;
            *(float2*)&C[o1] = v1;
        }
    }
}

// ---------------------------------------------------------------------------
// RoPE on Q (original order) and compacted K (angle from original position)
// ---------------------------------------------------------------------------
__global__ void rope2_kernel(float* __restrict__ Xq, float* __restrict__ Xk,
                             const float* __restrict__ cosb,
                             const float* __restrict__ sinb,
                             const int* __restrict__ cidx,
                             const int* __restrict__ cnt)
{
    long idx = (long)blockIdx.x * blockDim.x + threadIdx.x;  // 2 * 2^23
    int isK = (int)(idx >> 23);
    int t = (int)(idx & ((1 << 23) - 1));
    int i = t & 63;
    int h = (t >> 6) & 15;
    int s = (t >> 10) & 2047;
    int b = t >> 21;
    int s_ang = s;
    float* X = Xq;
    if (isK) {
        if (s >= cnt[b]) return;
        s_ang = cidx[b * Sz + s];
        X = Xk;
    }
    long base = ((long)(b * Sz + s)) * Dz + h * DHz + 2 * i;
    float c = cosb[s_ang * 64 + i], sn = sinb[s_ang * 64 + i];
    float x1 = X[base], x2 = X[base + 1];
    X[base]     = x1 * c - x2 * sn;
    X[base + 1] = x1 * sn + x2 * c;
}

// ===========================================================================
// Flash attention, tf32 mma, 64 q-rows per CTA (128 threads, 4 warps),
// P aliases K region. smem 100352 B -> 2 CTAs/SM. (unchanged from R15)
// ===========================================================================
#define FKP_OFF 8192
#define FV_OFF  (8192 + 8448)
#define FLM_FLOATS (8192 + 8448 + 8448)   // 25088
#define FLM_SMEM (FLM_FLOATS * 4)         // 100352 B

__global__ __launch_bounds__(128) void flashmma_kernel(
    const float* __restrict__ Q, const float* __restrict__ K,
    const float* __restrict__ V, const int* __restrict__ cnt,
    float* __restrict__ O)
{
    extern __shared__ float sf[];
    float* sQf = sf;
    float* sKf = sf + FKP_OFF;
    float* sPf = sf + FKP_OFF;   // alias: P overwrites K after S-phase
    float* sVf = sf + FV_OFF;

    const int tid = threadIdx.x;
    const int lane = tid & 31, w = tid >> 5;      // 4 warps
    const int g = lane >> 2, tig = lane & 3;
    const int blk = blockIdx.x;
    const int qt = blk & 31;
    const int h  = (blk >> 5) & 15;
    const int b  = blk >> 9;
    const int q0 = qt * 64;
    const int kmax = cnt[b];
    const float scale = 0.08838834764831845f;   // 1/sqrt(128)

    // ---- Q tile (64 x 128) -> A-fragment-major, tf32
    for (int idx = tid; idx < 64 * 128; idx += 128) {
        int row = idx >> 7, d = idx & 127;
        int sub = row >> 4, rr = row & 15, kb = d >> 3, c = d & 7;
        float v = Q[((long)(b * Sz + q0 + row)) * Dz + h * DHz + d];
        sQf[kb * 512 + sub * 128 + ((rr & 7) * 4 + (c & 3)) * 4
            + (rr >> 3) + 2 * (c >> 2)] = tf32r(v);
    }

    float m_i[2] = {-1e30f, -1e30f};
    float l_i[2] = {0.f, 0.f};
    float oacc[16][4];
#pragma unroll
    for (int ni = 0; ni < 16; ni++)
#pragma unroll
        for (int e = 0; e < 4; e++) oacc[ni][e] = 0.f;

    const int l2 = lane >> 1, l1 = lane & 1;

    const int ntiles = (kmax + 63) >> 6;
    for (int t = 0; t < ntiles; t++) {
        const int k0 = t << 6;
        __syncthreads();   // prev tile's P/V reads done (and Q visible at t=0)

        // ---- K/V producer: warp w handles keys w*16 .. w*16+15
#pragma unroll 4
        for (int i = 0; i < 16; i++) {
            int key = w * 16 + i;
            long gk = ((long)(b * Sz + k0 + key)) * Dz + h * DHz + lane * 4;
            float4 kq = *(const float4*)&K[gk];
            float4 vq = *(const float4*)&V[gk];
            int ntK = key >> 3, nnK = key & 7;
            int baseK = ntK * 1056 + l2 * 66 + nnK * 8 + l1;
            sKf[baseK + 0] = tf32r(kq.x);
            sKf[baseK + 2] = tf32r(kq.y);
            sKf[baseK + 4] = tf32r(kq.z);
            sKf[baseK + 6] = tf32r(kq.w);
            int kbV = key >> 3, kkV = key & 7;
            int baseV = kbV * 1056 + l2 * 66 + l1 * 32 + (kkV & 3) * 2 + (kkV >> 2);
            sVf[baseV + 0]  = tf32r(vq.x);
            sVf[baseV + 8]  = tf32r(vq.y);
            sVf[baseV + 16] = tf32r(vq.z);
            sVf[baseV + 24] = tf32r(vq.w);
        }
        __syncthreads();

        // ---- S = Q @ K^T  (warp: 16 rows x 64 keys)
        float sacc[8][4];
#pragma unroll
        for (int ni = 0; ni < 8; ni++)
#pragma unroll
            for (int e = 0; e < 4; e++) sacc[ni][e] = 0.f;

#pragma unroll
        for (int kb = 0; kb < 16; kb++) {
            uint4 af = *(const uint4*)&sQf[kb * 512 + w * 128 + lane * 4];
#pragma unroll
            for (int ni = 0; ni < 8; ni++) {
                uint2 bf = *(const uint2*)&sKf[ni * 1056 + kb * 66 + lane * 2];
                mma_tf32(sacc[ni], (const uint32_t*)&af, (const uint32_t*)&bf);
            }
        }
        __syncthreads();   // ALL warps done reading K before P overwrites it

        // ---- mask + scale; row maxima (rows g, g+8)
        float tm0 = -1e30f, tm1 = -1e30f;
#pragma unroll
        for (int ni = 0; ni < 8; ni++) {
            int key = k0 + ni * 8 + 2 * tig;
            bool ms0 = key >= kmax, ms1 = (key + 1) >= kmax;
            sacc[ni][0] = ms0 ? -1e30f : sacc[ni][0] * scale;
            sacc[ni][1] = ms1 ? -1e30f : sacc[ni][1] * scale;
            sacc[ni][2] = ms0 ? -1e30f : sacc[ni][2] * scale;
            sacc[ni][3] = ms1 ? -1e30f : sacc[ni][3] * scale;
            tm0 = fmaxf(tm0, fmaxf(sacc[ni][0], sacc[ni][1]));
            tm1 = fmaxf(tm1, fmaxf(sacc[ni][2], sacc[ni][3]));
        }
        tm0 = fmaxf(tm0, __shfl_xor_sync(0xffffffffu, tm0, 1));
        tm0 = fmaxf(tm0, __shfl_xor_sync(0xffffffffu, tm0, 2));
        tm1 = fmaxf(tm1, __shfl_xor_sync(0xffffffffu, tm1, 1));
        tm1 = fmaxf(tm1, __shfl_xor_sync(0xffffffffu, tm1, 2));

        float nm0 = fmaxf(m_i[0], tm0), nm1 = fmaxf(m_i[1], tm1);
        float corr0 = __expf(m_i[0] - nm0), corr1 = __expf(m_i[1] - nm1);

        // ---- exp, write P (A-frag-major, aliasing K), accumulate row sums
        float ps0 = 0.f, ps1 = 0.f;
        const int pbase = w * 128 + (g * 4 + ((2 * tig) & 3)) * 4 + 2 * (tig >> 1);
#pragma unroll
        for (int ni = 0; ni < 8; ni++) {
            float p0 = __expf(sacc[ni][0] - nm0);
            float p1 = __expf(sacc[ni][1] - nm0);
            float p2 = __expf(sacc[ni][2] - nm1);
            float p3 = __expf(sacc[ni][3] - nm1);
            ps0 += p0 + p1;
            ps1 += p2 + p3;
            float2 w0 = { tf32r(p0), tf32r(p2) };
            float2 w1 = { tf32r(p1), tf32r(p3) };
            *(float2*)&sPf[ni * 512 + pbase]     = w0;
            *(float2*)&sPf[ni * 512 + pbase + 4] = w1;
        }
        ps0 += __shfl_xor_sync(0xffffffffu, ps0, 1);
        ps0 += __shfl_xor_sync(0xffffffffu, ps0, 2);
        ps1 += __shfl_xor_sync(0xffffffffu, ps1, 1);
        ps1 += __shfl_xor_sync(0xffffffffu, ps1, 2);
        l_i[0] = l_i[0] * corr0 + ps0;  m_i[0] = nm0;
        l_i[1] = l_i[1] * corr1 + ps1;  m_i[1] = nm1;

#pragma unroll
        for (int ni = 0; ni < 16; ni++) {
            oacc[ni][0] *= corr0; oacc[ni][1] *= corr0;
            oacc[ni][2] *= corr1; oacc[ni][3] *= corr1;
        }
        __syncwarp();   // P region is warp-private: order STS before LDS

        // ---- O += P @ V  (warp: 16 rows x 128 d)
#pragma unroll
        for (int kb = 0; kb < 8; kb++) {
            uint4 af = *(const uint4*)&sPf[kb * 512 + w * 128 + lane * 4];
#pragma unroll
            for (int ni = 0; ni < 16; ni++) {
                uint2 bf = *(const uint2*)&sVf[kb * 1056 + ni * 66 + lane * 2];
                mma_tf32(oacc[ni], (const uint32_t*)&af, (const uint32_t*)&bf);
            }
        }
    }

    // ---- epilogue: normalize, store
    float inv0 = 1.f / l_i[0], inv1 = 1.f / l_i[1];
    int row0 = q0 + w * 16 + g;
#pragma unroll
    for (int ni = 0; ni < 16; ni++) {
        int col = h * DHz + ni * 8 + tig * 2;
        long o0 = ((long)(b * Sz + row0)) * Dz + col;
        long o1 = ((long)(b * Sz + row0 + 8)) * Dz + col;
        float2 v0 = { oacc[ni][0] * inv0, oacc[ni][1] * inv0 };
        float2 v1 = { oacc[ni][2] * inv1, oacc[ni][3] * inv1 };
        *(float2*)&O[o0] = v0;
        *(float2*)&O[o1] = v1;
    }
}

// ---------------------------------------------------------------------------
// LayerNorm over last dim (2048), one CTA per row
// ---------------------------------------------------------------------------
__global__ __launch_bounds__(256) void ln_kernel(
    const float* __restrict__ X, const float* __restrict__ gamma,
    const float* __restrict__ beta, float* __restrict__ Y)
{
    const int row = blockIdx.x;
    const int tid = threadIdx.x;
    const float* x = X + (long)row * Dz;

    float v[8], s = 0.f, s2 = 0.f;
#pragma unroll
    for (int r = 0; r < 8; r++) {
        float t = x[r * 256 + tid];
        v[r] = t; s += t; s2 += t * t;
    }
#pragma unroll
    for (int d = 16; d >= 1; d >>= 1) {
        s  += __shfl_xor_sync(0xffffffffu, s,  d);
        s2 += __shfl_xor_sync(0xffffffffu, s2, d);
    }
    __shared__ float rs[8], rs2[8];
    __shared__ float s_mean, s_rstd;
    int wid = tid >> 5, lane = tid & 31;
    if (lane == 0) { rs[wid] = s; rs2[wid] = s2; }
    __syncthreads();
    if (tid == 0) {
        float S = 0.f, S2 = 0.f;
        for (int w = 0; w < 8; w++) { S += rs[w]; S2 += rs2[w]; }
        float mu = S * (1.f / 2048.f);
        float var = S2 * (1.f / 2048.f) - mu * mu;
        s_mean = mu;
        s_rstd = rsqrtf(var + 1e-5f);
    }
    __syncthreads();
    float mu = s_mean, rstd = s_rstd;
    float* y = Y + (long)row * Dz;
#pragma unroll
    for (int r = 0; r < 8; r++) {
        int c = r * 256 + tid;
        y[c] = (v[r] - mu) * rstd * gamma[c] + beta[c];
    }
}

// ---------------------------------------------------------------------------
extern "C" void kernel_launch(void* const* d_in, const int* in_sizes, int n_in,
                              void* d_out, int out_size)
{
    const float* q_input  = (const float*)d_in[0];
    const float* kv_input = (const float*)d_in[1];
    const int*   mask     = (const int*)d_in[2];    // bool -> int32 in harness
    const float* Wq = (const float*)d_in[3];
    const float* Wk = (const float*)d_in[4];
    const float* Wv = (const float*)d_in[5];
    const float* Wo = (const float*)d_in[6];
    const float* ln_gamma = (const float*)d_in[7];
    const float* ln_beta  = (const float*)d_in[8];
    const float* rope_cos = (const float*)d_in[9];
    const float* rope_sin = (const float*)d_in[10];
    float* out = (float*)d_out;

    float *pQ, *pK, *pV, *pA, *pR, *pKVc;
    int *pcidx, *pcnt;
    cudaGetSymbolAddress((void**)&pQ, g_Q);
    cudaGetSymbolAddress((void**)&pK, g_K);
    cudaGetSymbolAddress((void**)&pV, g_V);
    cudaGetSymbolAddress((void**)&pA, g_A);
    cudaGetSymbolAddress((void**)&pR, g_R);
    cudaGetSymbolAddress((void**)&pKVc, g_KVc);
    cudaGetSymbolAddress((void**)&pcidx, g_cidx);
    cudaGetSymbolAddress((void**)&pcnt, g_cnt);

    cudaFuncSetAttribute(flashmma_kernel,
                         cudaFuncAttributeMaxDynamicSharedMemorySize, FLM_SMEM);
    cudaFuncSetAttribute(tgemm,
                         cudaFuncAttributeMaxDynamicSharedMemorySize, TG_SMEM);

    const int M = Bz * Sz;   // 8192
    dim3 gq(8, 64, 1), gkv(8, 64, 2);   // 256-wide N tiles

    // mask compaction + gather
    compact_kernel<<<Bz, 1024>>>(mask, pcidx, pcnt);
    gather_kernel<<<M, 256>>>(kv_input, pcidx, pcnt, pKVc);

    // projections (K/V on compacted rows, with early-exit)
    tgemm<<<gq, 256, TG_SMEM>>>(q_input, Wq, Wq, nullptr, pQ, pQ, nullptr);
    tgemm<<<gkv, 256, TG_SMEM>>>(pKVc, Wk, Wv, nullptr, pK, pV, pcnt);

    // RoPE (Q full; K compacted, angles from original positions)
    long rope_threads = 2L * Bz * Sz * NHz * 64;
    rope2_kernel<<<(int)(rope_threads / 256), 256>>>(pQ, pK, rope_cos, rope_sin,
                                                     pcidx, pcnt);

    // attention over compacted keys (tf32 mma flash, 64-row CTAs, 2/SM)
    flashmma_kernel<<<Bz * NHz * (Sz / 64), 128, FLM_SMEM>>>(pQ, pK, pV, pcnt, pA);

    // output projection + residual
    tgemm<<<gq, 256, TG_SMEM>>>(pA, Wo, Wo, q_input, pR, pR, nullptr);

    // LayerNorm
    ln_kernel<<<M, 256>>>(pR, ln_gamma, ln_beta, out);
}